// round 10
// baseline (speedup 1.0000x reference)
#include <cuda_runtime.h>
#include <cuda_fp16.h>

#define N_NODES 100000
#define N_EDGES 1600000
#define DIM 128
#define NB_SCAN 391   // ceil(100000/256)

// Scratch (allocation-free rule: __device__ globals)
__device__ __half g_xw[(size_t)N_NODES * DIM];  // 25.6 MB, fp16
__device__ float g_dis[N_NODES];
__device__ int   g_deg[N_NODES];
__device__ int   g_off[N_NODES];     // exclusive prefix of deg
__device__ int   g_cur[N_NODES];     // placement cursors
__device__ int   g_erow[N_EDGES];    // edge source, sorted by target
__device__ int   g_bsum[NB_SCAN];
__device__ int   g_orflag;           // OR of sampled odd int32 words; 0 => int64

// ---------------- zero deg counters (runs on GEMM side stream) ----------------
__global__ void k_zero() {
    int i = blockIdx.x * blockDim.x + threadIdx.x;
    if (i < N_NODES) g_deg[i] = 0;
}

// ---------------- dtype detect (1 block, sampled) ----------------
__global__ void k_detect(const int* __restrict__ ei32) {
    if (threadIdx.x == 0) g_orflag = 0;
    __syncthreads();
    int t = threadIdx.x;
    int acc = 0;
#pragma unroll
    for (int s = 0; s < 32; s++) {
        int j = t + s * 256;                  // 0..8191
        long long idx = (long long)j * 195;   // spread over ~1.6M entries
        acc |= ei32[2 * idx + 1];
    }
    if (acc != 0) atomicOr(&g_orflag, 1);
}

// ---------------- degree histogram: 4 edges/thread ----------------
__global__ void k_hist(const int* __restrict__ ei32) {
    int t = blockIdx.x * blockDim.x + threadIdx.x;   // 0 .. N_EDGES/4-1
    if (t >= N_EDGES / 4) return;
    if (g_orflag == 0) {
        // int64 layout: col half at word 2*N_EDGES; 2x int4 = 4 entries
        const int4* p = (const int4*)(ei32 + 2 * N_EDGES);
        int4 v0 = __ldg(&p[2 * t]);
        int4 v1 = __ldg(&p[2 * t + 1]);
        atomicAdd(&g_deg[v0.x], 1);
        atomicAdd(&g_deg[v0.z], 1);
        atomicAdd(&g_deg[v1.x], 1);
        atomicAdd(&g_deg[v1.z], 1);
    } else {
        // int32 layout: col half at word N_EDGES; int4 = 4 entries
        const int4* p = (const int4*)(ei32 + N_EDGES);
        int4 v = __ldg(&p[t]);
        atomicAdd(&g_deg[v.x], 1);
        atomicAdd(&g_deg[v.y], 1);
        atomicAdd(&g_deg[v.z], 1);
        atomicAdd(&g_deg[v.w], 1);
    }
}

// ---------------- scan1 (fused: also computes g_dis) ----------------
__global__ __launch_bounds__(256) void k_scan1() {
    __shared__ int s[256];
    int t = threadIdx.x;
    int i = blockIdx.x * 256 + t;
    int v = (i < N_NODES) ? g_deg[i] : 0;
    if (i < N_NODES) g_dis[i] = rsqrtf((float)(v + 1)); // +1 self loop
    s[t] = v; __syncthreads();
#pragma unroll
    for (int off = 1; off < 256; off <<= 1) {
        int tmp = (t >= off) ? s[t - off] : 0;
        __syncthreads();
        s[t] += tmp;
        __syncthreads();
    }
    if (i < N_NODES) g_off[i] = s[t] - v;      // block-local exclusive
    if (t == 255) g_bsum[blockIdx.x] = s[255];
}

// ---------------- scan2+3 fused ----------------
__global__ __launch_bounds__(256) void k_scan23() {
    __shared__ int red[256];
    int t = threadIdx.x;
    int base = 0;
    for (int j = t; j < blockIdx.x; j += 256) base += g_bsum[j];
    red[t] = base; __syncthreads();
#pragma unroll
    for (int off = 128; off > 0; off >>= 1) {
        if (t < off) red[t] += red[t + off];
        __syncthreads();
    }
    int boff = red[0];
    int i = blockIdx.x * 256 + t;
    if (i < N_NODES) {
        int o = g_off[i] + boff;
        g_off[i] = o;
        g_cur[i] = o;
    }
}

// ---------------- place edges into CSR buckets: 4 edges/thread ----------------
__global__ void k_place(const int* __restrict__ ei32) {
    int t = blockIdx.x * blockDim.x + threadIdx.x;   // 0 .. N_EDGES/4-1
    if (t >= N_EDGES / 4) return;
    int r[4], c[4];
    if (g_orflag == 0) {
        const int4* pr = (const int4*)ei32;
        const int4* pc = (const int4*)(ei32 + 2 * N_EDGES);
        int4 vr0 = __ldg(&pr[2 * t]);
        int4 vr1 = __ldg(&pr[2 * t + 1]);
        int4 vc0 = __ldg(&pc[2 * t]);
        int4 vc1 = __ldg(&pc[2 * t + 1]);
        r[0] = vr0.x; r[1] = vr0.z; r[2] = vr1.x; r[3] = vr1.z;
        c[0] = vc0.x; c[1] = vc0.z; c[2] = vc1.x; c[3] = vc1.z;
    } else {
        int4 vr = __ldg(&((const int4*)ei32)[t]);
        int4 vc = __ldg(&((const int4*)(ei32 + N_EDGES))[t]);
        r[0] = vr.x; r[1] = vr.y; r[2] = vr.z; r[3] = vr.w;
        c[0] = vc.x; c[1] = vc.y; c[2] = vc.z; c[3] = vc.w;
    }
#pragma unroll
    for (int j = 0; j < 4; j++) {
        int p = atomicAdd(&g_cur[c[j]], 1);
        g_erow[p] = r[j];
    }
}

// ---------------- tf32 tensor-core GEMM: g_xw = fp16(x @ W) ----------------
__global__ __launch_bounds__(256) void k_gemm(const float* __restrict__ x,
                                              const float* __restrict__ W) {
    __shared__ unsigned As[128][36];
    __shared__ unsigned Bs[32][136];
    const int m0   = blockIdx.x * 128;
    const int tid  = threadIdx.x;
    const int warp = tid >> 5;
    const int lane = tid & 31;
    const int wm   = warp >> 1;
    const int wn   = warp & 1;
    const int qr   = lane >> 2;
    const int qc   = lane & 3;

    float acc[2][8][4];
#pragma unroll
    for (int mi = 0; mi < 2; mi++)
#pragma unroll
        for (int ni = 0; ni < 8; ni++)
#pragma unroll
            for (int j = 0; j < 4; j++) acc[mi][ni][j] = 0.f;

#pragma unroll 1
    for (int kt = 0; kt < 4; kt++) {
#pragma unroll
        for (int i = 0; i < 16; i++) {
            int idx = tid + i * 256;
            int r = idx >> 5, c = idx & 31;
            int gr = m0 + r;
            float v = (gr < N_NODES) ? __ldg(&x[(size_t)gr * DIM + kt * 32 + c]) : 0.f;
            unsigned u;
            asm("cvt.rna.tf32.f32 %0, %1;" : "=r"(u) : "f"(v));
            As[r][c] = u;
        }
#pragma unroll
        for (int i = 0; i < 16; i++) {
            int idx = tid + i * 256;
            int r = idx >> 7, c = idx & 127;
            float v = __ldg(&W[(kt * 32 + r) * DIM + c]);
            unsigned u;
            asm("cvt.rna.tf32.f32 %0, %1;" : "=r"(u) : "f"(v));
            Bs[r][c] = u;
        }
        __syncthreads();

#pragma unroll
        for (int ks = 0; ks < 4; ks++) {
            const int k0 = ks * 8;
            unsigned a[2][4], bf[8][2];
#pragma unroll
            for (int mi = 0; mi < 2; mi++) {
                int rb = wm * 32 + mi * 16;
                a[mi][0] = As[rb + qr][k0 + qc];
                a[mi][1] = As[rb + qr + 8][k0 + qc];
                a[mi][2] = As[rb + qr][k0 + qc + 4];
                a[mi][3] = As[rb + qr + 8][k0 + qc + 4];
            }
#pragma unroll
            for (int ni = 0; ni < 8; ni++) {
                int cb = wn * 64 + ni * 8;
                bf[ni][0] = Bs[k0 + qc][cb + qr];
                bf[ni][1] = Bs[k0 + qc + 4][cb + qr];
            }
#pragma unroll
            for (int mi = 0; mi < 2; mi++)
#pragma unroll
                for (int ni = 0; ni < 8; ni++) {
                    asm volatile(
                        "mma.sync.aligned.m16n8k8.row.col.f32.tf32.tf32.f32 "
                        "{%0,%1,%2,%3}, {%4,%5,%6,%7}, {%8,%9}, {%0,%1,%2,%3};"
                        : "+f"(acc[mi][ni][0]), "+f"(acc[mi][ni][1]),
                          "+f"(acc[mi][ni][2]), "+f"(acc[mi][ni][3])
                        : "r"(a[mi][0]), "r"(a[mi][1]), "r"(a[mi][2]), "r"(a[mi][3]),
                          "r"(bf[ni][0]), "r"(bf[ni][1]));
                }
        }
        __syncthreads();
    }

#pragma unroll
    for (int mi = 0; mi < 2; mi++) {
        int r0 = m0 + wm * 32 + mi * 16 + qr;
        int r1 = r0 + 8;
#pragma unroll
        for (int ni = 0; ni < 8; ni++) {
            int cb = wn * 64 + ni * 8 + qc * 2;
            if (r0 < N_NODES)
                *(__half2*)&g_xw[(size_t)r0 * DIM + cb] =
                    __floats2half2_rn(acc[mi][ni][0], acc[mi][ni][1]);
            if (r1 < N_NODES)
                *(__half2*)&g_xw[(size_t)r1 * DIM + cb] =
                    __floats2half2_rn(acc[mi][ni][2], acc[mi][ni][3]);
        }
    }
}

// ---------------- CSR gather: warp/node, 2 edges/instr, 8-edge unroll ----------------
__device__ __forceinline__ void hacc(float* a, const uint4& u, float w) {
    float2 f0 = __half22float2(*(const __half2*)&u.x);
    float2 f1 = __half22float2(*(const __half2*)&u.y);
    float2 f2 = __half22float2(*(const __half2*)&u.z);
    float2 f3 = __half22float2(*(const __half2*)&u.w);
    a[0] += f0.x * w; a[1] += f0.y * w;
    a[2] += f1.x * w; a[3] += f1.y * w;
    a[4] += f2.x * w; a[5] += f2.y * w;
    a[6] += f3.x * w; a[7] += f3.y * w;
}

__global__ __launch_bounds__(256) void k_gather(const float* __restrict__ b,
                                                float* __restrict__ out) {
    int n    = (blockIdx.x * blockDim.x + threadIdx.x) >> 5;
    int lane = threadIdx.x & 31;
    if (n >= N_NODES) return;
    int half = lane >> 4;      // 0 or 1
    int l16  = lane & 15;

    const uint4* xw4 = (const uint4*)g_xw;   // row stride = 16 uint4
    float dn = g_dis[n];

    float a[8];
#pragma unroll
    for (int i = 0; i < 8; i++) a[i] = 0.f;

    // self-loop: half 0 carries weight dn*dn, half 1 contributes 0
    {
        uint4 u = __ldg(&xw4[(size_t)n * 16 + l16]);
        hacc(a, u, (half == 0) ? dn * dn : 0.f);
    }

    int beg = g_off[n];
    int end = (n + 1 < N_NODES) ? g_off[n + 1] : N_EDGES;

    int e = beg;
    // 8 edges per warp-iteration (4 per half-warp, 4 rows in flight per lane)
    for (; e + 7 < end; e += 8) {
        int r0 = __ldg(&g_erow[e + half]);
        int r1 = __ldg(&g_erow[e + 2 + half]);
        int r2 = __ldg(&g_erow[e + 4 + half]);
        int r3 = __ldg(&g_erow[e + 6 + half]);
        float w0 = __ldg(&g_dis[r0]) * dn;
        float w1 = __ldg(&g_dis[r1]) * dn;
        float w2 = __ldg(&g_dis[r2]) * dn;
        float w3 = __ldg(&g_dis[r3]) * dn;
        uint4 u0 = __ldg(&xw4[(size_t)r0 * 16 + l16]);
        uint4 u1 = __ldg(&xw4[(size_t)r1 * 16 + l16]);
        uint4 u2 = __ldg(&xw4[(size_t)r2 * 16 + l16]);
        uint4 u3 = __ldg(&xw4[(size_t)r3 * 16 + l16]);
        hacc(a, u0, w0);
        hacc(a, u1, w1);
        hacc(a, u2, w2);
        hacc(a, u3, w3);
    }
    // 4-edge
    for (; e + 3 < end; e += 4) {
        int r0 = __ldg(&g_erow[e + half]);
        int r1 = __ldg(&g_erow[e + 2 + half]);
        float w0 = __ldg(&g_dis[r0]) * dn;
        float w1 = __ldg(&g_dis[r1]) * dn;
        uint4 u0 = __ldg(&xw4[(size_t)r0 * 16 + l16]);
        uint4 u1 = __ldg(&xw4[(size_t)r1 * 16 + l16]);
        hacc(a, u0, w0);
        hacc(a, u1, w1);
    }
    // tail: predicated 2 edges per iteration
    for (; e < end; e += 2) {
        int idx = e + half;
        bool valid = idx < end;
        int r0 = valid ? __ldg(&g_erow[idx]) : n;
        float w0 = valid ? __ldg(&g_dis[r0]) * dn : 0.f;
        uint4 u0 = __ldg(&xw4[(size_t)r0 * 16 + l16]);
        hacc(a, u0, w0);
    }

    // combine halves
#pragma unroll
    for (int i = 0; i < 8; i++)
        a[i] += __shfl_xor_sync(0xffffffffu, a[i], 16);

    if (half == 0) {
        float4 b0 = ((const float4*)b)[l16 * 2];
        float4 b1 = ((const float4*)b)[l16 * 2 + 1];
        float4 o0 = make_float4(fmaxf(a[0] + b0.x, 0.f), fmaxf(a[1] + b0.y, 0.f),
                                fmaxf(a[2] + b0.z, 0.f), fmaxf(a[3] + b0.w, 0.f));
        float4 o1 = make_float4(fmaxf(a[4] + b1.x, 0.f), fmaxf(a[5] + b1.y, 0.f),
                                fmaxf(a[6] + b1.z, 0.f), fmaxf(a[7] + b1.w, 0.f));
        ((float4*)out)[(size_t)n * 32 + l16 * 2]     = o0;
        ((float4*)out)[(size_t)n * 32 + l16 * 2 + 1] = o1;
    }
}

extern "C" void kernel_launch(void* const* d_in, const int* in_sizes, int n_in,
                              void* d_out, int out_size) {
    // Identify inputs by element count:
    //   x: 12,800,000   edge_index: 3,200,000   W: 16,384   b: 128
    const float* x  = nullptr;
    const void*  ei = nullptr;
    const float* W  = nullptr;
    const float* b  = nullptr;
    for (int i = 0; i < n_in; i++) {
        switch (in_sizes[i]) {
            case 12800000: x  = (const float*)d_in[i]; break;
            case 3200000:  ei = d_in[i];               break;
            case 16384:    W  = (const float*)d_in[i]; break;
            case 128:      b  = (const float*)d_in[i]; break;
            default: break;
        }
    }
    float* out = (float*)d_out;
    const int* ei32 = (const int*)ei;

    // Side stream: zero g_deg (needed by hist) then GEMM (needed by gather).
    cudaStream_t s2;
    cudaStreamCreateWithFlags(&s2, cudaStreamNonBlocking);
    cudaEvent_t ev_fork, ev_zero, ev_join;
    cudaEventCreateWithFlags(&ev_fork, cudaEventDisableTiming);
    cudaEventCreateWithFlags(&ev_zero, cudaEventDisableTiming);
    cudaEventCreateWithFlags(&ev_join, cudaEventDisableTiming);

    cudaEventRecord(ev_fork, 0);
    cudaStreamWaitEvent(s2, ev_fork, 0);
    k_zero<<<(N_NODES + 255) / 256, 256, 0, s2>>>();
    cudaEventRecord(ev_zero, s2);
    k_gemm<<<(N_NODES + 127) / 128, 256, 0, s2>>>(x, W);
    cudaEventRecord(ev_join, s2);

    // main-stream preprocessing chain
    k_detect<<<1, 256>>>(ei32);
    cudaStreamWaitEvent(0, ev_zero, 0);
    k_hist<<<(N_EDGES / 4 + 255) / 256, 256>>>(ei32);
    k_scan1<<<NB_SCAN, 256>>>();
    k_scan23<<<NB_SCAN, 256>>>();
    k_place<<<(N_EDGES / 4 + 255) / 256, 256>>>(ei32);

    cudaStreamWaitEvent(0, ev_join, 0);
    {
        long long total_threads = (long long)N_NODES * 32;
        int blocks = (int)((total_threads + 255) / 256);
        k_gather<<<blocks, 256>>>(b, out);
    }
}

// round 11
// speedup vs baseline: 1.0675x; 1.0675x over previous
#include <cuda_runtime.h>
#include <cuda_fp16.h>

#define N_NODES 100000
#define N_EDGES 1600000
#define DIM 128
#define CAP 64            // bucket capacity; overflow side-list handles the rest

// Scratch (allocation-free rule: __device__ globals)
__device__ __half g_xw[(size_t)N_NODES * DIM];        // 25.6 MB, fp16
__device__ float g_dis[N_NODES];
__device__ int   g_cnt[N_NODES];                      // per-node in-degree counters
__device__ int   g_slots[(size_t)N_NODES * CAP];      // 25.6 MB bucket storage
__device__ int   g_ovr[N_EDGES];                      // overflow rows (normally unused)
__device__ int   g_ovc[N_EDGES];                      // overflow cols
__device__ int   g_ovcnt;
__device__ int   g_orflag;  // OR of sampled odd int32 words; 0 => int64

// ---------------- zero counters (runs on GEMM side stream) ----------------
__global__ void k_zero() {
    int i = blockIdx.x * blockDim.x + threadIdx.x;
    if (i < N_NODES) g_cnt[i] = 0;
    if (i == 0) g_ovcnt = 0;
}

// ---------------- dtype detect (1 block, sampled) ----------------
__global__ void k_detect(const int* __restrict__ ei32) {
    if (threadIdx.x == 0) g_orflag = 0;
    __syncthreads();
    int t = threadIdx.x;
    int acc = 0;
#pragma unroll
    for (int s = 0; s < 32; s++) {
        int j = t + s * 256;                  // 0..8191
        long long idx = (long long)j * 195;   // spread over ~1.6M entries
        acc |= ei32[2 * idx + 1];
    }
    if (acc != 0) atomicOr(&g_orflag, 1);
}

// ---------------- single-pass place into fixed-capacity buckets ----------------
__global__ void k_place(const int* __restrict__ ei32) {
    int t = blockIdx.x * blockDim.x + threadIdx.x;   // 0 .. N_EDGES/2-1
    if (t >= N_EDGES / 2) return;
    int r0, r1, c0, c1;
    if (g_orflag == 0) {     // int64: low words
        int4 vr = __ldg(&((const int4*)ei32)[t]);
        int4 vc = __ldg(&((const int4*)(ei32 + 2 * N_EDGES))[t]);
        r0 = vr.x; r1 = vr.z;
        c0 = vc.x; c1 = vc.z;
    } else {                 // int32
        int2 vr = __ldg(&((const int2*)ei32)[t]);
        int2 vc = __ldg(&((const int2*)(ei32 + N_EDGES))[t]);
        r0 = vr.x; r1 = vr.y;
        c0 = vc.x; c1 = vc.y;
    }
    int p0 = atomicAdd(&g_cnt[c0], 1);
    if (p0 < CAP) g_slots[(size_t)c0 * CAP + p0] = r0;
    else { int o = atomicAdd(&g_ovcnt, 1); g_ovr[o] = r0; g_ovc[o] = c0; }
    int p1 = atomicAdd(&g_cnt[c1], 1);
    if (p1 < CAP) g_slots[(size_t)c1 * CAP + p1] = r1;
    else { int o = atomicAdd(&g_ovcnt, 1); g_ovr[o] = r1; g_ovc[o] = c1; }
}

// ---------------- dis = rsqrt(deg+1) from final counts ----------------
__global__ void k_dis() {
    int i = blockIdx.x * blockDim.x + threadIdx.x;
    if (i < N_NODES) g_dis[i] = rsqrtf((float)(g_cnt[i] + 1));
}

// ---------------- tf32 tensor-core GEMM: g_xw = fp16(x @ W) ----------------
__global__ __launch_bounds__(256) void k_gemm(const float* __restrict__ x,
                                              const float* __restrict__ W) {
    __shared__ unsigned As[128][36];
    __shared__ unsigned Bs[32][136];
    const int m0   = blockIdx.x * 128;
    const int tid  = threadIdx.x;
    const int warp = tid >> 5;
    const int lane = tid & 31;
    const int wm   = warp >> 1;
    const int wn   = warp & 1;
    const int qr   = lane >> 2;
    const int qc   = lane & 3;

    float acc[2][8][4];
#pragma unroll
    for (int mi = 0; mi < 2; mi++)
#pragma unroll
        for (int ni = 0; ni < 8; ni++)
#pragma unroll
            for (int j = 0; j < 4; j++) acc[mi][ni][j] = 0.f;

#pragma unroll 1
    for (int kt = 0; kt < 4; kt++) {
#pragma unroll
        for (int i = 0; i < 16; i++) {
            int idx = tid + i * 256;
            int r = idx >> 5, c = idx & 31;
            int gr = m0 + r;
            float v = (gr < N_NODES) ? __ldg(&x[(size_t)gr * DIM + kt * 32 + c]) : 0.f;
            unsigned u;
            asm("cvt.rna.tf32.f32 %0, %1;" : "=r"(u) : "f"(v));
            As[r][c] = u;
        }
#pragma unroll
        for (int i = 0; i < 16; i++) {
            int idx = tid + i * 256;
            int r = idx >> 7, c = idx & 127;
            float v = __ldg(&W[(kt * 32 + r) * DIM + c]);
            unsigned u;
            asm("cvt.rna.tf32.f32 %0, %1;" : "=r"(u) : "f"(v));
            Bs[r][c] = u;
        }
        __syncthreads();

#pragma unroll
        for (int ks = 0; ks < 4; ks++) {
            const int k0 = ks * 8;
            unsigned a[2][4], bf[8][2];
#pragma unroll
            for (int mi = 0; mi < 2; mi++) {
                int rb = wm * 32 + mi * 16;
                a[mi][0] = As[rb + qr][k0 + qc];
                a[mi][1] = As[rb + qr + 8][k0 + qc];
                a[mi][2] = As[rb + qr][k0 + qc + 4];
                a[mi][3] = As[rb + qr + 8][k0 + qc + 4];
            }
#pragma unroll
            for (int ni = 0; ni < 8; ni++) {
                int cb = wn * 64 + ni * 8;
                bf[ni][0] = Bs[k0 + qc][cb + qr];
                bf[ni][1] = Bs[k0 + qc + 4][cb + qr];
            }
#pragma unroll
            for (int mi = 0; mi < 2; mi++)
#pragma unroll
                for (int ni = 0; ni < 8; ni++) {
                    asm volatile(
                        "mma.sync.aligned.m16n8k8.row.col.f32.tf32.tf32.f32 "
                        "{%0,%1,%2,%3}, {%4,%5,%6,%7}, {%8,%9}, {%0,%1,%2,%3};"
                        : "+f"(acc[mi][ni][0]), "+f"(acc[mi][ni][1]),
                          "+f"(acc[mi][ni][2]), "+f"(acc[mi][ni][3])
                        : "r"(a[mi][0]), "r"(a[mi][1]), "r"(a[mi][2]), "r"(a[mi][3]),
                          "r"(bf[ni][0]), "r"(bf[ni][1]));
                }
        }
        __syncthreads();
    }

#pragma unroll
    for (int mi = 0; mi < 2; mi++) {
        int r0 = m0 + wm * 32 + mi * 16 + qr;
        int r1 = r0 + 8;
#pragma unroll
        for (int ni = 0; ni < 8; ni++) {
            int cb = wn * 64 + ni * 8 + qc * 2;
            if (r0 < N_NODES)
                *(__half2*)&g_xw[(size_t)r0 * DIM + cb] =
                    __floats2half2_rn(acc[mi][ni][0], acc[mi][ni][1]);
            if (r1 < N_NODES)
                *(__half2*)&g_xw[(size_t)r1 * DIM + cb] =
                    __floats2half2_rn(acc[mi][ni][2], acc[mi][ni][3]);
        }
    }
}

// ---------------- bucket gather: warp/node, 2 edges per warp-instruction ----------------
__device__ __forceinline__ void hacc(float* a, const uint4& u, float w) {
    float2 f0 = __half22float2(*(const __half2*)&u.x);
    float2 f1 = __half22float2(*(const __half2*)&u.y);
    float2 f2 = __half22float2(*(const __half2*)&u.z);
    float2 f3 = __half22float2(*(const __half2*)&u.w);
    a[0] += f0.x * w; a[1] += f0.y * w;
    a[2] += f1.x * w; a[3] += f1.y * w;
    a[4] += f2.x * w; a[5] += f2.y * w;
    a[6] += f3.x * w; a[7] += f3.y * w;
}

__global__ __launch_bounds__(256) void k_gather(const float* __restrict__ b,
                                                float* __restrict__ out) {
    int n    = (blockIdx.x * blockDim.x + threadIdx.x) >> 5;
    int lane = threadIdx.x & 31;
    if (n >= N_NODES) return;
    int half = lane >> 4;      // 0 or 1
    int l16  = lane & 15;

    const uint4* xw4 = (const uint4*)g_xw;   // row stride = 16 uint4
    const int* bucket = g_slots + (size_t)n * CAP;
    float dn = g_dis[n];

    float a[8];
#pragma unroll
    for (int i = 0; i < 8; i++) a[i] = 0.f;

    // self-loop: half 0 carries weight dn*dn, half 1 contributes 0
    {
        uint4 u = __ldg(&xw4[(size_t)n * 16 + l16]);
        hacc(a, u, (half == 0) ? dn * dn : 0.f);
    }

    int deg = g_cnt[n];
    int end = (deg < CAP) ? deg : CAP;

    int e = 0;
    // 4 edges per warp-iteration (2 per half-warp)
    for (; e + 3 < end; e += 4) {
        int r0 = __ldg(&bucket[e + half]);
        int r1 = __ldg(&bucket[e + 2 + half]);
        float w0 = __ldg(&g_dis[r0]) * dn;
        float w1 = __ldg(&g_dis[r1]) * dn;
        uint4 u0 = __ldg(&xw4[(size_t)r0 * 16 + l16]);
        uint4 u1 = __ldg(&xw4[(size_t)r1 * 16 + l16]);
        hacc(a, u0, w0);
        hacc(a, u1, w1);
    }
    // tail: predicated 2 edges per iteration
    for (; e < end; e += 2) {
        int idx = e + half;
        bool valid = idx < end;
        int r0 = valid ? __ldg(&bucket[idx]) : n;
        float w0 = valid ? __ldg(&g_dis[r0]) * dn : 0.f;
        uint4 u0 = __ldg(&xw4[(size_t)r0 * 16 + l16]);
        hacc(a, u0, w0);
    }

    // overflow edges (normally zero) — exact correctness for any input
    int ov = g_ovcnt;
    for (int i = 0; i < ov; i++) {
        if (__ldg(&g_ovc[i]) == n) {
            int r = __ldg(&g_ovr[i]);
            float w = __ldg(&g_dis[r]) * dn;
            uint4 u = __ldg(&xw4[(size_t)r * 16 + l16]);
            hacc(a, u, (half == 0) ? w : 0.f);
        }
    }

    // combine halves
#pragma unroll
    for (int i = 0; i < 8; i++)
        a[i] += __shfl_xor_sync(0xffffffffu, a[i], 16);

    if (half == 0) {
        float4 b0 = ((const float4*)b)[l16 * 2];
        float4 b1 = ((const float4*)b)[l16 * 2 + 1];
        float4 o0 = make_float4(fmaxf(a[0] + b0.x, 0.f), fmaxf(a[1] + b0.y, 0.f),
                                fmaxf(a[2] + b0.z, 0.f), fmaxf(a[3] + b0.w, 0.f));
        float4 o1 = make_float4(fmaxf(a[4] + b1.x, 0.f), fmaxf(a[5] + b1.y, 0.f),
                                fmaxf(a[6] + b1.z, 0.f), fmaxf(a[7] + b1.w, 0.f));
        ((float4*)out)[(size_t)n * 32 + l16 * 2]     = o0;
        ((float4*)out)[(size_t)n * 32 + l16 * 2 + 1] = o1;
    }
}

extern "C" void kernel_launch(void* const* d_in, const int* in_sizes, int n_in,
                              void* d_out, int out_size) {
    // Identify inputs by element count:
    //   x: 12,800,000   edge_index: 3,200,000   W: 16,384   b: 128
    const float* x  = nullptr;
    const void*  ei = nullptr;
    const float* W  = nullptr;
    const float* b  = nullptr;
    for (int i = 0; i < n_in; i++) {
        switch (in_sizes[i]) {
            case 12800000: x  = (const float*)d_in[i]; break;
            case 3200000:  ei = d_in[i];               break;
            case 16384:    W  = (const float*)d_in[i]; break;
            case 128:      b  = (const float*)d_in[i]; break;
            default: break;
        }
    }
    float* out = (float*)d_out;
    const int* ei32 = (const int*)ei;

    // Side stream: zero counters (needed by place), then GEMM (needed by gather).
    cudaStream_t s2;
    cudaStreamCreateWithFlags(&s2, cudaStreamNonBlocking);
    cudaEvent_t ev_fork, ev_zero, ev_join;
    cudaEventCreateWithFlags(&ev_fork, cudaEventDisableTiming);
    cudaEventCreateWithFlags(&ev_zero, cudaEventDisableTiming);
    cudaEventCreateWithFlags(&ev_join, cudaEventDisableTiming);

    cudaEventRecord(ev_fork, 0);
    cudaStreamWaitEvent(s2, ev_fork, 0);
    k_zero<<<(N_NODES + 255) / 256, 256, 0, s2>>>();
    cudaEventRecord(ev_zero, s2);
    k_gemm<<<(N_NODES + 127) / 128, 256, 0, s2>>>(x, W);
    cudaEventRecord(ev_join, s2);

    // main-stream chain: detect -> place -> dis -> gather
    k_detect<<<1, 256>>>(ei32);
    cudaStreamWaitEvent(0, ev_zero, 0);
    k_place<<<(N_EDGES / 2 + 255) / 256, 256>>>(ei32);
    k_dis<<<(N_NODES + 255) / 256, 256>>>();

    cudaStreamWaitEvent(0, ev_join, 0);
    {
        long long total_threads = (long long)N_NODES * 32;
        int blocks = (int)((total_threads + 255) / 256);
        k_gather<<<blocks, 256>>>(b, out);
    }
}